// round 1
// baseline (speedup 1.0000x reference)
#include <cuda_runtime.h>
#include <math.h>

#define NPT 8192
#define L2E 1.4426950408889634f
#define LN2 0.6931471805599453f
#define LOG_AB -9.010913347279288f   // log(1/8192)

#define RPW 8        // rows per warp (register-tiled)
#define WARPS 8      // warps per CTA
#define TILE 1024    // columns staged in smem per tile
#define ROWS_PER_CTA (RPW * WARPS)            // 64
#define CTAS_PER_PROB (NPT / ROWS_PER_CTA)    // 128

// Persistent scratch (no allocation allowed in kernel_launch)
__device__ float  d_f[NPT], d_g[NPT], d_pp[NPT], d_qq[NPT];
__device__ float  d_x2h[NPT], d_y2h[NPT];
__device__ float4 d_colF[NPT], d_colG[NPT], d_colP[NPT], d_colQ[NPT];

__global__ void init_kernel(const float* __restrict__ X, const float* __restrict__ Y) {
    int i = blockIdx.x * blockDim.x + threadIdx.x;
    if (i >= NPT) return;
    float x0 = X[3*i], x1 = X[3*i+1], x2 = X[3*i+2];
    d_x2h[i] = 0.5f * (x0*x0 + x1*x1 + x2*x2);
    float y0 = Y[3*i], y1 = Y[3*i+1], y2 = Y[3*i+2];
    d_y2h[i] = 0.5f * (y0*y0 + y1*y1 + y2*y2);
    d_f[i] = 0.f; d_g[i] = 0.f; d_pp[i] = 0.f; d_qq[i] = 0.f;
}

// Snapshot the column-side data for the 4 softmin problems at this eps.
// colF: reduce over y with dual g  (f update)
// colG: reduce over x with dual f  (g update)
// colP: reduce over x with dual pp (pp update)
// colQ: reduce over y with dual qq (qq update)
__global__ void prep_kernel(float eps, const float* __restrict__ X, const float* __restrict__ Y) {
    int i = blockIdx.x * blockDim.x + threadIdx.x;
    if (i >= NPT) return;
    float x0 = X[3*i], x1 = X[3*i+1], x2 = X[3*i+2];
    float y0 = Y[3*i], y1 = Y[3*i+1], y2 = Y[3*i+2];
    float x2h = d_x2h[i], y2h = d_y2h[i];
    d_colF[i] = make_float4(y0, y1, y2, L2E * (LOG_AB + (d_g[i]  - y2h) / eps));
    d_colG[i] = make_float4(x0, x1, x2, L2E * (LOG_AB + (d_f[i]  - x2h) / eps));
    d_colP[i] = make_float4(x0, x1, x2, L2E * (LOG_AB + (d_pp[i] - x2h) / eps));
    d_colQ[i] = make_float4(y0, y1, y2, L2E * (LOG_AB + (d_qq[i] - y2h) / eps));
}

__global__ void __launch_bounds__(256)
phase_kernel(float eps, int avg, const float* __restrict__ X, const float* __restrict__ Y) {
    __shared__ float4 tile[TILE];

    int prob = blockIdx.x >> 7;           // blockIdx / CTAS_PER_PROB
    int rb   = blockIdx.x & (CTAS_PER_PROB - 1);

    const float4* __restrict__ cols;
    const float* __restrict__ rowsP;
    const float* __restrict__ rh2;
    float* pot;
    if (prob == 0)      { cols = d_colF; rowsP = X; rh2 = d_x2h; pot = d_f;  }
    else if (prob == 1) { cols = d_colG; rowsP = Y; rh2 = d_y2h; pot = d_g;  }
    else if (prob == 2) { cols = d_colP; rowsP = X; rh2 = d_x2h; pot = d_pp; }
    else                { cols = d_colQ; rowsP = Y; rh2 = d_y2h; pot = d_qq; }

    int warp = threadIdx.x >> 5;
    int lane = threadIdx.x & 31;
    int rowBase = rb * ROWS_PER_CTA + warp * RPW;

    float sc = L2E / eps;
    float a0[RPW], a1[RPW], a2[RPW], m[RPW], S[RPW];
#pragma unroll
    for (int r = 0; r < RPW; r++) {
        int row = rowBase + r;
        a0[r] = rowsP[3*row]     * sc;
        a1[r] = rowsP[3*row + 1] * sc;
        a2[r] = rowsP[3*row + 2] * sc;
        m[r] = -1e30f;
        S[r] = 0.f;
    }

    for (int tb = 0; tb < NPT; tb += TILE) {
#pragma unroll
        for (int k = 0; k < TILE / 256; k++)
            tile[threadIdx.x + k * 256] = cols[tb + threadIdx.x + k * 256];
        __syncthreads();

#pragma unroll 4
        for (int k = 0; k < TILE / 32; k++) {
            float4 c = tile[k * 32 + lane];
#pragma unroll
            for (int r = 0; r < RPW; r++) {
                float t  = fmaf(a0[r], c.x, fmaf(a1[r], c.y, fmaf(a2[r], c.z, c.w)));
                float mn = fmaxf(m[r], t);
                S[r] = fmaf(S[r], exp2f(m[r] - mn), exp2f(t - mn));
                m[r] = mn;
            }
        }
        __syncthreads();
    }

    // warp-level (m, S) combine
#pragma unroll
    for (int r = 0; r < RPW; r++) {
#pragma unroll
        for (int off = 16; off > 0; off >>= 1) {
            float mo = __shfl_xor_sync(0xffffffffu, m[r], off);
            float So = __shfl_xor_sync(0xffffffffu, S[r], off);
            float mn = fmaxf(m[r], mo);
            S[r] = S[r] * exp2f(m[r] - mn) + So * exp2f(mo - mn);
            m[r] = mn;
        }
    }

    if (lane == 0) {
#pragma unroll
        for (int r = 0; r < RPW; r++) {
            int row = rowBase + r;
            float res = rh2[row] - eps * LN2 * (m[r] + log2f(S[r]));
            pot[row] = avg ? 0.5f * (pot[row] + res) : res;
        }
    }
}

__global__ void reduce_kernel(float* out, int out_size) {
    __shared__ double sh[256];
    double s = 0.0;
    for (int i = threadIdx.x; i < NPT; i += 256)
        s += (double)(d_f[i] - d_pp[i]) + (double)(d_g[i] - d_qq[i]);
    sh[threadIdx.x] = s;
    __syncthreads();
    for (int o = 128; o > 0; o >>= 1) {
        if (threadIdx.x < o) sh[threadIdx.x] += sh[threadIdx.x + o];
        __syncthreads();
    }
    if (threadIdx.x == 0) {
        float v = (float)(sh[0] / (double)NPT);
        for (int k = 0; k < out_size; k++) out[k] = v;
    }
}

extern "C" void kernel_launch(void* const* d_in, const int* in_sizes, int n_in,
                              void* d_out, int out_size) {
    const float* X = (const float*)d_in[0];   // source_points [8192,3]
    const float* Y = (const float*)d_in[1];   // target_points [8192,3]

    // geomloss eps schedule in double, matching reference exactly
    double sched[96];
    int ns = 0;
    double e      = pow(2.0, 2.0);     // DIAMETER ** P
    double target = pow(0.01, 2.0);    // BLUR ** P
    double ratio  = pow(0.9, 2.0);     // SCALING ** P
    while (e > target) { sched[ns++] = e; e *= ratio; }

    init_kernel<<<NPT / 256, 256>>>(X, Y);

    // phase 0: init (duals zero, avg=0, eps=sched[0])
    // phases 1..ns: scan body over full schedule (avg=1)
    // phase ns+1: final extrapolation at eps_final (avg=0)
    for (int p = 0; p <= ns + 1; p++) {
        float eps; int avg;
        if (p == 0)       { eps = (float)sched[0];     avg = 0; }
        else if (p <= ns) { eps = (float)sched[p - 1]; avg = 1; }
        else              { eps = (float)target;       avg = 0; }
        prep_kernel<<<NPT / 256, 256>>>(eps, X, Y);
        phase_kernel<<<4 * CTAS_PER_PROB, 256>>>(eps, avg, X, Y);
    }

    reduce_kernel<<<1, 256>>>((float*)d_out, out_size);
}